// round 2
// baseline (speedup 1.0000x reference)
#include <cuda_runtime.h>
#include <math.h>
#include <stdint.h>

// Problem constants
#define BSZ 256
#define RR  196
#define TT  26
#define DD  512
#define AVN 3000
#define BT  (BSZ*TT)   // 6656

// ---------------- scratch layout ----------------
constexpr size_t N_SIMG      = (size_t)BSZ*DD;
constexpr size_t N_IMGSUM    = (size_t)BSZ*DD;
constexpr size_t N_X         = (size_t)BT*DD;
constexpr size_t N_WORDSUM   = (size_t)BSZ*DD;
constexpr size_t N_WCOMB     = (size_t)DD*3584;
constexpr size_t N_Y         = (size_t)BT*3584;
constexpr size_t N_PHRASE    = (size_t)BT*DD;
constexpr size_t N_PHRASESUM = (size_t)BSZ*DD;
constexpr size_t N_XG        = (size_t)BT*2048;
constexpr size_t N_G         = (size_t)BSZ*2048;
constexpr size_t N_H         = (size_t)BSZ*DD;
constexpr size_t N_C         = (size_t)BSZ*DD;
constexpr size_t N_SENT      = (size_t)BSZ*DD;
constexpr size_t N_V1        = (size_t)BSZ*DD;
constexpr size_t N_HW        = (size_t)BSZ*DD;
constexpr size_t N_CAT       = (size_t)BSZ*1024;
constexpr size_t N_HP        = (size_t)BSZ*DD;
constexpr size_t N_HS        = (size_t)BSZ*DD;

constexpr size_t O_SIMG      = 0;
constexpr size_t O_IMGSUM    = O_SIMG + N_SIMG;
constexpr size_t O_X         = O_IMGSUM + N_IMGSUM;
constexpr size_t O_WORDSUM   = O_X + N_X;
constexpr size_t O_WCOMB     = O_WORDSUM + N_WORDSUM;
constexpr size_t O_Y         = O_WCOMB + N_WCOMB;
constexpr size_t O_PHRASE    = O_Y + N_Y;
constexpr size_t O_PHRASESUM = O_PHRASE + N_PHRASE;
constexpr size_t O_XG        = O_PHRASESUM + N_PHRASESUM;
constexpr size_t O_G         = O_XG + N_XG;
constexpr size_t O_H         = O_G + N_G;
constexpr size_t O_C         = O_H + N_H;
constexpr size_t O_SENT      = O_C + N_C;
constexpr size_t O_V1        = O_SENT + N_SENT;
constexpr size_t O_HW        = O_V1 + N_V1;
constexpr size_t O_CAT       = O_HW + N_HW;
constexpr size_t O_HP        = O_CAT + N_CAT;
constexpr size_t O_HS        = O_HP + N_HP;
constexpr size_t SCRATCH_FLOATS = O_HS + N_HS;

__device__ float g_scratch[SCRATCH_FLOATS];

__device__ __forceinline__ float sigmoidf_(float x) { return 1.f / (1.f + __expf(-x)); }

// ---------------- kernels ----------------

// S_img[b,d] = sum_r image_feat[b,r,d]
__global__ void reduce_img(const float* __restrict__ img, float* __restrict__ out) {
    int b = blockIdx.x, d = threadIdx.x;
    const float* p = img + (size_t)b * RR * DD + d;
    float s = 0.f;
#pragma unroll 4
    for (int r = 0; r < RR; ++r) s += p[(size_t)r * DD];
    out[b * DD + d] = s;
}

// X[row,d] = emb[qenc[row], d]   (row = b*26+t)
__global__ void gather_word(const int* __restrict__ q, const float* __restrict__ emb,
                            float* __restrict__ X) {
    int row = blockIdx.x, d = threadIdx.x;
    int tok = q[row];
    X[(size_t)row * DD + d] = emb[(size_t)tok * DD + d];
}

// dst[b,d] = sum_t src[(b*26+t), d]
__global__ void reduce26(const float* __restrict__ src, float* __restrict__ dst) {
    int b = blockIdx.x, d = threadIdx.x;
    float s = 0.f;
#pragma unroll
    for (int t = 0; t < TT; ++t) s += src[((size_t)b * TT + t) * DD + d];
    dst[b * DD + d] = s;
}

// Build combined conv weight Wcomb[512][3584] (row-major [k][n])
// blocks: 0 uni | 1 bi-center | 2 bi->next (k>=256) | 3 bi->prev (k<256)
//         4 tri-center | 5 tri->next | 6 tri->prev
__global__ void build_wcomb(const float* __restrict__ Wu, const float* __restrict__ Wb,
                            const float* __restrict__ Wt, float* __restrict__ Wc) {
    int idx = blockIdx.x * 256 + threadIdx.x;           // 512*3584 total
    int k = idx / 3584, n = idx % 3584;
    int blk = n >> 9, d = n & 511;
    float v = 0.f;
    if (blk == 0)      v = Wu[k * 512 + d];
    else if (blk == 1) v = Wb[(256 + k) * 512 + d];
    else if (blk == 2) { if (k >= 256) v = Wb[(k - 256) * 512 + d]; }
    else if (blk == 3) { if (k < 256)  v = Wb[(768 + k) * 512 + d]; }
    else if (blk == 4) v = Wt[(512 + k) * 512 + d];
    else if (blk == 5) v = Wt[k * 512 + d];
    else               v = Wt[(1024 + k) * 512 + d];
    Wc[idx] = v;
}

// phrase[row,d] = max(uni, bi, tri) with shifted neighbor contributions
__global__ void combine_phrase(const float* __restrict__ Y,
                               const float* __restrict__ b_uni,
                               const float* __restrict__ b_bi,
                               const float* __restrict__ b_tri,
                               float* __restrict__ phrase) {
    int row = blockIdx.x, d = threadIdx.x;
    int t = row % TT;
    const float* y = Y + (size_t)row * 3584;
    float u  = y[d] + b_uni[d];
    float bi = y[512 + d] + b_bi[d];
    if (t > 0)      bi += Y[(size_t)(row - 1) * 3584 + 1024 + d];
    if (t < TT - 1) bi += Y[(size_t)(row + 1) * 3584 + 1536 + d];
    float tr = y[2048 + d] + b_tri[d];
    if (t > 0)      tr += Y[(size_t)(row - 1) * 3584 + 2560 + d];
    if (t < TT - 1) tr += Y[(size_t)(row + 1) * 3584 + 3072 + d];
    phrase[(size_t)row * DD + d] = fmaxf(u, fmaxf(bi, tr));
}

// LSTM gate update. G has per-b row stride gstride; gates i,f,cg,o at +0,+512,+1024,+1536
__global__ void lstm_gates(const float* __restrict__ G, long gstride,
                           float* __restrict__ h, float* __restrict__ c,
                           float* __restrict__ sentsum, int t) {
    int b = blockIdx.x, d = threadIdx.x;
    const float* g = G + (size_t)b * gstride;
    float iv = g[d], fv = g[512 + d], cgv = g[1024 + d], ov = g[1536 + d];
    float cprev = (t == 0) ? 0.f : c[b * DD + d];
    float cnew = sigmoidf_(fv) * cprev + sigmoidf_(iv) * tanhf(cgv);
    float hnew = sigmoidf_(ov) * tanhf(cnew);
    c[b * DD + d] = cnew;
    h[b * DD + d] = hnew;
    sentsum[b * DD + d] = (t == 0) ? hnew : (sentsum[b * DD + d] + hnew);
}

__global__ void ew_add(const float* __restrict__ a, const float* __restrict__ b,
                       float* __restrict__ o) {
    int i = blockIdx.x * 256 + threadIdx.x;
    o[i] = a[i] + b[i];
}

// cat[b, 0:512] = a+b ; cat[b, 512:1024] = h2
__global__ void ew_cat(const float* __restrict__ a, const float* __restrict__ b,
                       const float* __restrict__ h2, float* __restrict__ o) {
    int bb = blockIdx.x, d = threadIdx.x;
    o[(size_t)bb * 1024 + d]       = a[bb * DD + d] + b[bb * DD + d];
    o[(size_t)bb * 1024 + 512 + d] = h2[bb * DD + d];
}

// ---------------- GEMM: 128x128x8, 256 threads, 8x8/thread, reg-prefetch ----------------
// C[M,N] = A[M,K] @ B[K,N] (+bias). M,N multiples of 128; K multiple of 8.
__global__ __launch_bounds__(256) void sgemm128(
    const float* __restrict__ A, const float* __restrict__ B, float* __restrict__ C,
    int M, int N, int K, const float* __restrict__ bias)
{
    __shared__ float As[8][128];
    __shared__ float Bs[8][128];
    int tid = threadIdx.x;
    int m0 = blockIdx.y * 128;
    int n0 = blockIdx.x * 128;
    int tx = tid & 15, ty = tid >> 4;

    int ar = tid >> 1;            // 0..127
    int ak = (tid & 1) * 4;       // 0 or 4
    int bk = tid >> 5;            // 0..7
    int bn = (tid & 31) * 4;      // 0..124

    const float* Aptr = A + (size_t)(m0 + ar) * K + ak;
    const float* Bptr = B + (size_t)bk * N + n0 + bn;

    float4 aReg = *(const float4*)Aptr;
    float4 bReg = *(const float4*)Bptr;

    float acc[8][8];
#pragma unroll
    for (int i = 0; i < 8; i++)
#pragma unroll
        for (int j = 0; j < 8; j++) acc[i][j] = 0.f;

    int nk = K >> 3;
    for (int kt = 0; kt < nk; ++kt) {
        As[ak + 0][ar] = aReg.x; As[ak + 1][ar] = aReg.y;
        As[ak + 2][ar] = aReg.z; As[ak + 3][ar] = aReg.w;
        *(float4*)&Bs[bk][bn] = bReg;
        __syncthreads();
        if (kt + 1 < nk) {
            aReg = *(const float4*)(Aptr + (kt + 1) * 8);
            bReg = *(const float4*)(Bptr + (size_t)(kt + 1) * 8 * N);
        }
#pragma unroll
        for (int kk = 0; kk < 8; ++kk) {
            float4 a0 = *(const float4*)&As[kk][ty * 4];
            float4 a1 = *(const float4*)&As[kk][64 + ty * 4];
            float4 b0 = *(const float4*)&Bs[kk][tx * 4];
            float4 b1 = *(const float4*)&Bs[kk][64 + tx * 4];
            float av[8] = {a0.x, a0.y, a0.z, a0.w, a1.x, a1.y, a1.z, a1.w};
            float bv[8] = {b0.x, b0.y, b0.z, b0.w, b1.x, b1.y, b1.z, b1.w};
#pragma unroll
            for (int i = 0; i < 8; i++)
#pragma unroll
                for (int j = 0; j < 8; j++) acc[i][j] += av[i] * bv[j];
        }
        __syncthreads();
    }

#pragma unroll
    for (int qi = 0; qi < 2; ++qi)
#pragma unroll
        for (int i = 0; i < 4; ++i) {
            int row = m0 + qi * 64 + ty * 4 + i;
#pragma unroll
            for (int qj = 0; qj < 2; ++qj) {
                int col = n0 + qj * 64 + tx * 4;
                float4 v;
                v.x = acc[qi * 4 + i][qj * 4 + 0];
                v.y = acc[qi * 4 + i][qj * 4 + 1];
                v.z = acc[qi * 4 + i][qj * 4 + 2];
                v.w = acc[qi * 4 + i][qj * 4 + 3];
                if (bias) {
                    v.x += bias[col + 0]; v.y += bias[col + 1];
                    v.z += bias[col + 2]; v.w += bias[col + 3];
                }
                *(float4*)&C[(size_t)row * N + col] = v;
            }
        }
}

// ---------------- GEMM: 64x64x8, 256 threads, 4x4/thread, flexible epilogue -------------
// C = A@B + biasScale*bias + addPtr[row*addStride + col]; act==1 -> tanh.
// M multiple of 64, K multiple of 8; N arbitrary (guarded).
__global__ __launch_bounds__(256) void sgemm64(
    const float* __restrict__ A, const float* __restrict__ B, float* __restrict__ C,
    int M, int N, int K,
    const float* __restrict__ bias, float biasScale, int act,
    const float* __restrict__ addPtr, long addStride)
{
    __shared__ float As[8][64];
    __shared__ float Bs[8][64];
    int tid = threadIdx.x;
    int m0 = blockIdx.y * 64;
    int n0 = blockIdx.x * 64;
    int tx = tid & 15, ty = tid >> 4;

    bool isA = tid < 128;
    int ar = tid >> 1;            // A loader: row 0..63
    int ak = (tid & 1) * 4;
    int u  = tid - 128;
    int bk = u >> 4;              // B loader: k 0..7
    int bn = (u & 15) * 4;

    const float* Aptr = A + (size_t)(m0 + (isA ? ar : 0)) * K + (isA ? ak : 0);
    int bcol = n0 + bn;
    const float* Bptr = B + (size_t)bk * N + bcol;

    float4 aReg = make_float4(0.f, 0.f, 0.f, 0.f);
    float4 bReg = make_float4(0.f, 0.f, 0.f, 0.f);
    if (isA) aReg = *(const float4*)Aptr;
    else {
        if (bcol + 3 < N) bReg = *(const float4*)Bptr;
        else {
            bReg.x = (bcol + 0 < N) ? Bptr[0] : 0.f;
            bReg.y = (bcol + 1 < N) ? Bptr[1] : 0.f;
            bReg.z = (bcol + 2 < N) ? Bptr[2] : 0.f;
            bReg.w = (bcol + 3 < N) ? Bptr[3] : 0.f;
        }
    }

    float acc[4][4];
#pragma unroll
    for (int i = 0; i < 4; i++)
#pragma unroll
        for (int j = 0; j < 4; j++) acc[i][j] = 0.f;

    int nk = K >> 3;
    for (int kt = 0; kt < nk; ++kt) {
        if (isA) {
            As[ak + 0][ar] = aReg.x; As[ak + 1][ar] = aReg.y;
            As[ak + 2][ar] = aReg.z; As[ak + 3][ar] = aReg.w;
        } else {
            *(float4*)&Bs[bk][bn] = bReg;
        }
        __syncthreads();
        if (kt + 1 < nk) {
            if (isA) aReg = *(const float4*)(Aptr + (kt + 1) * 8);
            else {
                const float* bp = Bptr + (size_t)(kt + 1) * 8 * N;
                if (bcol + 3 < N) bReg = *(const float4*)bp;
                else {
                    bReg.x = (bcol + 0 < N) ? bp[0] : 0.f;
                    bReg.y = (bcol + 1 < N) ? bp[1] : 0.f;
                    bReg.z = (bcol + 2 < N) ? bp[2] : 0.f;
                    bReg.w = (bcol + 3 < N) ? bp[3] : 0.f;
                }
            }
        }
#pragma unroll
        for (int kk = 0; kk < 8; ++kk) {
            float4 a = *(const float4*)&As[kk][ty * 4];
            float4 bv4 = *(const float4*)&Bs[kk][tx * 4];
            float av[4] = {a.x, a.y, a.z, a.w};
            float bv[4] = {bv4.x, bv4.y, bv4.z, bv4.w};
#pragma unroll
            for (int i = 0; i < 4; i++)
#pragma unroll
                for (int j = 0; j < 4; j++) acc[i][j] += av[i] * bv[j];
        }
        __syncthreads();
    }

#pragma unroll
    for (int i = 0; i < 4; i++) {
        int row = m0 + ty * 4 + i;
#pragma unroll
        for (int j = 0; j < 4; j++) {
            int col = n0 + tx * 4 + j;
            if (col >= N) continue;
            float v = acc[i][j];
            if (bias)   v += bias[col] * biasScale;
            if (addPtr) v += addPtr[(size_t)row * addStride + col];
            if (act)    v = tanhf(v);
            C[(size_t)row * N + col] = v;
        }
    }
}

// ---------------- launch ----------------
extern "C" void kernel_launch(void* const* d_in, const int* in_sizes, int n_in,
                              void* d_out, int out_size) {
    const float* image_feat = (const float*)d_in[0];
    const int*   qenc       = (const int*)d_in[1];
    const float* W_ip   = (const float*)d_in[2];
    const float* b_ip   = (const float*)d_in[3];
    const float* emb    = (const float*)d_in[4];
    const float* W_uni  = (const float*)d_in[5];
    const float* b_uni  = (const float*)d_in[6];
    const float* W_bi   = (const float*)d_in[7];
    const float* b_bi   = (const float*)d_in[8];
    const float* W_tri  = (const float*)d_in[9];
    const float* b_tri  = (const float*)d_in[10];
    const float* Wx     = (const float*)d_in[11];
    const float* Wh     = (const float*)d_in[12];
    const float* b_lstm = (const float*)d_in[13];
    // d_in[14..23]: W_c,b_c,W_v,b_v,W_q,b_q,W_ai,b_ai,W_at,b_at — dead (softmax over 1 logit == 1)
    const float* W_w    = (const float*)d_in[24];
    const float* b_w    = (const float*)d_in[25];
    const float* W_p    = (const float*)d_in[26];
    const float* b_p    = (const float*)d_in[27];
    const float* W_s    = (const float*)d_in[28];
    const float* b_s    = (const float*)d_in[29];
    const float* W_f    = (const float*)d_in[30];
    const float* b_f    = (const float*)d_in[31];
    float* out = (float*)d_out;

    float* S = nullptr;
    cudaGetSymbolAddress((void**)&S, g_scratch);
    float* Simg      = S + O_SIMG;
    float* imgsum    = S + O_IMGSUM;
    float* X         = S + O_X;
    float* wordsum   = S + O_WORDSUM;
    float* Wcomb     = S + O_WCOMB;
    float* Y         = S + O_Y;
    float* phrase    = S + O_PHRASE;
    float* phrasesum = S + O_PHRASESUM;
    float* XG        = S + O_XG;
    float* G         = S + O_G;
    float* h         = S + O_H;
    float* c         = S + O_C;
    float* sentsum   = S + O_SENT;
    float* v1        = S + O_V1;
    float* hw        = S + O_HW;
    float* cat       = S + O_CAT;
    float* hp        = S + O_HP;
    float* hs        = S + O_HS;

    // image path: sum over regions, then one small affine
    reduce_img<<<BSZ, DD>>>(image_feat, Simg);
    sgemm64<<<dim3(8, 4), 256>>>(Simg, W_ip, imgsum, 256, 512, 512,
                                 b_ip, (float)RR, 0, nullptr, 0);

    // word path
    build_wcomb<<<(512 * 3584) / 256, 256>>>(W_uni, W_bi, W_tri, Wcomb);
    gather_word<<<BT, DD>>>(qenc, emb, X);
    reduce26<<<BSZ, DD>>>(X, wordsum);

    // phrase = max(uni, bi, tri) via one fused GEMM + shifted combine
    sgemm128<<<dim3(3584 / 128, BT / 128), 256>>>(X, Wcomb, Y, BT, 3584, 512, nullptr);
    combine_phrase<<<BT, DD>>>(Y, b_uni, b_bi, b_tri, phrase);
    reduce26<<<BSZ, DD>>>(phrase, phrasesum);

    // LSTM: precompute x@Wx + b, then 26 recurrent steps
    sgemm128<<<dim3(2048 / 128, BT / 128), 256>>>(phrase, Wx, XG, BT, 2048, 512, b_lstm);
    lstm_gates<<<BSZ, DD>>>(XG, (long)TT * 2048, h, c, sentsum, 0);
    for (int t = 1; t < TT; ++t) {
        sgemm64<<<dim3(32, 4), 256>>>(h, Wh, G, 256, 2048, 512,
                                      nullptr, 0.f, 0, XG + (size_t)t * 2048, (long)TT * 2048);
        lstm_gates<<<BSZ, DD>>>(G, 2048L, h, c, sentsum, t);
    }

    // heads
    ew_add<<<(BSZ * DD) / 256, 256>>>(imgsum, wordsum, v1);
    sgemm64<<<dim3(8, 4), 256>>>(v1, W_w, hw, 256, 512, 512, b_w, 1.f, 1, nullptr, 0);
    ew_cat<<<BSZ, DD>>>(imgsum, phrasesum, hw, cat);
    sgemm64<<<dim3(8, 4), 256>>>(cat, W_p, hp, 256, 512, 1024, b_p, 1.f, 1, nullptr, 0);
    ew_cat<<<BSZ, DD>>>(imgsum, sentsum, hp, cat);
    sgemm64<<<dim3(8, 4), 256>>>(cat, W_s, hs, 256, 512, 1024, b_s, 1.f, 1, nullptr, 0);

    // final classifier
    sgemm64<<<dim3((AVN + 63) / 64, 4), 256>>>(hs, W_f, out, 256, AVN, 512,
                                               b_f, 1.f, 0, nullptr, 0);
}